// round 2
// baseline (speedup 1.0000x reference)
#include <cuda_runtime.h>
#include <cstdint>

// Problem constants
#define B_   2
#define S_   4096
#define H_   16
#define D_   128
#define HID_ 2048
#define C_   128
#define NC_  32
#define M_   (B_*S_)   // 8192 rows
#define EPS_ 1e-6f

// ---------------- scratch (device globals; no allocs allowed) ----------------
__device__ float g_qf[(size_t)M_*HID_];
__device__ float g_kf[(size_t)M_*HID_];
__device__ float g_v [(size_t)M_*HID_];
__device__ float g_attn[(size_t)M_*HID_];
__device__ float g_kv[(size_t)B_*H_*NC_*D_*D_];   // [B][H][NC][D][D]
__device__ float g_ks[(size_t)B_*H_*NC_*D_];      // [B][H][NC][D]

// ---------------------------------------------------------------------------
// GEMM: out[M,N] = A[M,K] @ W[K,N] + bias, optional elu+1 epilogue.
// M=8192, N=K=2048. tf32 mma.sync m16n8k8, BM=BN=128, BK=32, 256 thr,
// cp.async double buffered.
// ---------------------------------------------------------------------------
#define GBM 128
#define GBN 128
#define GBK 32
#define ASTR 36     // A smem stride (floats) -> conflict-free frag reads
#define BSTR 136    // B smem stride
#define NKT (HID_/GBK)  // 64

__device__ __forceinline__ unsigned f2tf(float x) {
    unsigned u; asm("cvt.rna.tf32.f32 %0, %1;" : "=r"(u) : "f"(x)); return u;
}
__device__ __forceinline__ void cpasync16(void* s, const void* g) {
    unsigned sa = (unsigned)__cvta_generic_to_shared(s);
    asm volatile("cp.async.cg.shared.global [%0], [%1], 16;\n" :: "r"(sa), "l"(g));
}

extern __shared__ float dynsmem[];

__global__ __launch_bounds__(256)
void gemm_tf32_kernel(const float* __restrict__ A, const float* __restrict__ W,
                      const float* __restrict__ bias, float* __restrict__ out,
                      int act)
{
    float* As = dynsmem;                       // 2 * 128*36
    float* Bs = dynsmem + 2*GBM*ASTR;          // 2 * 32*136

    const int t  = threadIdx.x;
    const int bm = blockIdx.y, bn = blockIdx.x;
    const int lane = t & 31, warp = t >> 5;
    const int wm = warp >> 1, wn = warp & 1;   // 4 x 2 warp grid (M x N)
    const int g  = lane >> 2, tg = lane & 3;

    auto load_tile = [&](int kt, int buf) {
        const float* Ag = A + (size_t)(bm*128)*HID_ + kt*GBK;
        float* Ad = As + buf*GBM*ASTR;
        #pragma unroll
        for (int i = 0; i < 4; i++) {
            int row = (t >> 3) + i*32;
            int col4 = (t & 7) * 4;
            cpasync16(&Ad[row*ASTR + col4], Ag + (size_t)row*HID_ + col4);
        }
        const float* Wg = W + (size_t)(kt*GBK)*HID_ + bn*128;
        float* Bd = Bs + buf*GBK*BSTR;
        #pragma unroll
        for (int i = 0; i < 4; i++) {
            int row = (t >> 5) + i*8;
            int col4 = (t & 31) * 4;
            cpasync16(&Bd[row*BSTR + col4], Wg + (size_t)row*HID_ + col4);
        }
        asm volatile("cp.async.commit_group;\n");
    };

    float acc[2][8][4];
    #pragma unroll
    for (int mi = 0; mi < 2; mi++)
        #pragma unroll
        for (int ni = 0; ni < 8; ni++)
            #pragma unroll
            for (int q = 0; q < 4; q++) acc[mi][ni][q] = 0.f;

    load_tile(0, 0);

    for (int kt = 0; kt < NKT; kt++) {
        int buf = kt & 1;
        if (kt + 1 < NKT) {
            load_tile(kt + 1, buf ^ 1);
            asm volatile("cp.async.wait_group 1;\n");
        } else {
            asm volatile("cp.async.wait_group 0;\n");
        }
        __syncthreads();

        const float* Ab = As + buf*GBM*ASTR;
        const float* Bb = Bs + buf*GBK*BSTR;

        #pragma unroll
        for (int kk = 0; kk < 4; kk++) {
            unsigned a[2][4], b[8][2];
            #pragma unroll
            for (int mi = 0; mi < 2; mi++) {
                int r0 = wm*32 + mi*16 + g;
                a[mi][0] = f2tf(Ab[ r0      *ASTR + kk*8 + tg    ]);
                a[mi][1] = f2tf(Ab[(r0 + 8) *ASTR + kk*8 + tg    ]);
                a[mi][2] = f2tf(Ab[ r0      *ASTR + kk*8 + tg + 4]);
                a[mi][3] = f2tf(Ab[(r0 + 8) *ASTR + kk*8 + tg + 4]);
            }
            #pragma unroll
            for (int ni = 0; ni < 8; ni++) {
                int c0 = wn*64 + ni*8 + g;
                b[ni][0] = f2tf(Bb[(kk*8 + tg    )*BSTR + c0]);
                b[ni][1] = f2tf(Bb[(kk*8 + tg + 4)*BSTR + c0]);
            }
            #pragma unroll
            for (int mi = 0; mi < 2; mi++)
                #pragma unroll
                for (int ni = 0; ni < 8; ni++) {
                    asm volatile(
                        "mma.sync.aligned.m16n8k8.row.col.f32.tf32.tf32.f32 "
                        "{%0,%1,%2,%3},{%4,%5,%6,%7},{%8,%9},{%0,%1,%2,%3};\n"
                        : "+f"(acc[mi][ni][0]), "+f"(acc[mi][ni][1]),
                          "+f"(acc[mi][ni][2]), "+f"(acc[mi][ni][3])
                        : "r"(a[mi][0]), "r"(a[mi][1]), "r"(a[mi][2]), "r"(a[mi][3]),
                          "r"(b[ni][0]), "r"(b[ni][1]));
                }
        }
        __syncthreads();
    }

    // epilogue: bias (+ elu+1)
    #pragma unroll
    for (int mi = 0; mi < 2; mi++) {
        int row0 = bm*128 + wm*32 + mi*16 + g;
        #pragma unroll
        for (int ni = 0; ni < 8; ni++) {
            int col = bn*128 + wn*64 + ni*8 + 2*tg;
            float b0 = bias[col], b1 = bias[col + 1];
            float v0 = acc[mi][ni][0] + b0;
            float v1 = acc[mi][ni][1] + b1;
            float v2 = acc[mi][ni][2] + b0;
            float v3 = acc[mi][ni][3] + b1;
            if (act) {
                v0 = (v0 > 0.f) ? v0 + 1.f : __expf(v0);
                v1 = (v1 > 0.f) ? v1 + 1.f : __expf(v1);
                v2 = (v2 > 0.f) ? v2 + 1.f : __expf(v2);
                v3 = (v3 > 0.f) ? v3 + 1.f : __expf(v3);
            }
            float2 p0; p0.x = v0; p0.y = v1;
            float2 p1; p1.x = v2; p1.y = v3;
            *(float2*)&out[(size_t) row0     *HID_ + col] = p0;
            *(float2*)&out[(size_t)(row0 + 8)*HID_ + col] = p1;
        }
    }
}

// ---------------------------------------------------------------------------
// Chunk KV: per (b,h,n): kv[d,e] = sum_c kf[c,d]*v[c,e]; ksum[d] = sum_c kf[c,d]
// ---------------------------------------------------------------------------
__global__ __launch_bounds__(256)
void chunk_kv_kernel()
{
    __shared__ float skf[16*129];
    __shared__ float sv [16*129];

    const int t = threadIdx.x;
    const int lane = t & 31, warp = t >> 5;
    const int tdw = lane >> 3, tew = lane & 7;      // 4(d) x 8(e) in-warp
    const int wd  = warp >> 1, we  = warp & 1;      // 4(d) x 2(e) warps
    const int d0 = (wd*4 + tdw) * 8;
    const int e0 = (we*8 + tew) * 8;

    const int x = blockIdx.x;             // (b*H + h)*NC + n
    const int b = x / (H_*NC_);
    const int r = x % (H_*NC_);
    const int h = r / NC_;
    const int n = r % NC_;

    const size_t base = ((size_t)(b*S_ + n*C_))*HID_ + h*D_;

    float acc[8][8];
    float ks[8];
    #pragma unroll
    for (int i = 0; i < 8; i++) { ks[i] = 0.f;
        #pragma unroll
        for (int j = 0; j < 8; j++) acc[i][j] = 0.f; }

    for (int ct = 0; ct < 8; ct++) {
        #pragma unroll
        for (int rep = 0; rep < 8; rep++) {
            int lin = t + rep*256;
            int row = lin >> 7, d = lin & 127;
            size_t ga = base + (size_t)(ct*16 + row)*HID_ + d;
            skf[row*129 + d] = g_kf[ga];
            sv [row*129 + d] = g_v [ga];
        }
        __syncthreads();
        #pragma unroll 4
        for (int cc = 0; cc < 16; cc++) {
            float a[8], bb[8];
            #pragma unroll
            for (int i = 0; i < 8; i++) a[i]  = skf[cc*129 + d0 + i];
            #pragma unroll
            for (int j = 0; j < 8; j++) bb[j] = sv [cc*129 + e0 + j];
            #pragma unroll
            for (int i = 0; i < 8; i++) {
                ks[i] += a[i];
                #pragma unroll
                for (int j = 0; j < 8; j++)
                    acc[i][j] = fmaf(a[i], bb[j], acc[i][j]);
            }
        }
        __syncthreads();
    }

    const size_t kvb = (size_t)x * (D_*D_);
    #pragma unroll
    for (int i = 0; i < 8; i++)
        #pragma unroll
        for (int j = 0; j < 8; j++)
            g_kv[kvb + (size_t)(d0 + i)*D_ + e0 + j] = acc[i][j];

    if (we == 0 && tew == 0) {
        #pragma unroll
        for (int i = 0; i < 8; i++)
            g_ks[(size_t)x*D_ + d0 + i] = ks[i];
    }
}

// ---------------------------------------------------------------------------
// In-place exclusive scans over the chunk axis
// ---------------------------------------------------------------------------
__global__ __launch_bounds__(256)
void scan_kv_kernel()
{
    int f = blockIdx.x * 256 + threadIdx.x;      // B*H*D*D threads
    int bh = f >> 14;
    int de = f & 16383;
    float* p = g_kv + (size_t)bh * (NC_*D_*D_) + de;
    float run = 0.f;
    #pragma unroll
    for (int n = 0; n < NC_; n++) {
        float tv = p[(size_t)n * (D_*D_)];
        p[(size_t)n * (D_*D_)] = run;
        run += tv;
    }
}

__global__ __launch_bounds__(256)
void scan_ks_kernel()
{
    int f = blockIdx.x * 256 + threadIdx.x;      // B*H*D threads
    int bh = f >> 7;
    int d  = f & 127;
    float* p = g_ks + (size_t)bh * (NC_*D_) + d;
    float run = 0.f;
    #pragma unroll
    for (int n = 0; n < NC_; n++) {
        float tv = p[n*D_];
        p[n*D_] = run;
        run += tv;
    }
}

// ---------------------------------------------------------------------------
// Per-chunk attention:
//   A = mask(qf @ kf^T); z = rowsum(A) + qf@ksum_ex + EPS
//   out = (A @ v + qf @ kv_ex) / z
// Smem: s_q[128x129], s_B[128x129] (kf, then reused for masked A),
//       s_t[16x129] op2 tiles, s_ks[128], s_z[128]  (~141 KB dynamic)
// ---------------------------------------------------------------------------
#define CS_Q   0
#define CS_B   (128*129)
#define CS_T   (2*128*129)
#define CS_KS  (2*128*129 + 16*129)
#define CS_Z   (CS_KS + 128)
#define CS_TOT (CS_Z + 128)

__global__ __launch_bounds__(256)
void chunk_attn_kernel()
{
    extern __shared__ float cs[];
    float* s_q  = cs + CS_Q;
    float* s_B  = cs + CS_B;
    float* s_t  = cs + CS_T;
    float* s_ks = cs + CS_KS;
    float* s_z  = cs + CS_Z;

    const int t = threadIdx.x;
    const int lane = t & 31, warp = t >> 5;
    const int tcw = lane >> 3, tkw = lane & 7;   // 4(c) x 8(k/e)
    const int wc  = warp >> 1, wk  = warp & 1;
    const int c0 = (wc*4 + tcw) * 8;
    const int k0 = (wk*8 + tkw) * 8;

    const int x = blockIdx.x;             // (b*H + h)*NC + n
    const int b = x / (H_*NC_);
    const int r = x % (H_*NC_);
    const int h = r / NC_;
    const int n = r % NC_;

    const size_t base = ((size_t)(b*S_ + n*C_))*HID_ + h*D_;   // qf/kf/v/out chunk
    const size_t kvb  = (size_t)x * (D_*D_);

    // load qf, kf (full 128x128), ksum_ex
    #pragma unroll
    for (int rep = 0; rep < 64; rep++) {
        int lin = t + rep*256;
        int row = lin >> 7, d = lin & 127;
        size_t ga = base + (size_t)row*HID_ + d;
        s_q[row*129 + d] = g_qf[ga];
        s_B[row*129 + d] = g_kf[ga];
    }
    if (t < 128) s_ks[t] = g_ks[(size_t)x*D_ + t];
    __syncthreads();

    // Phase 1: A = qf @ kf^T (reduce over d)
    float acc[8][8];
    #pragma unroll
    for (int i = 0; i < 8; i++)
        #pragma unroll
        for (int j = 0; j < 8; j++) acc[i][j] = 0.f;

    #pragma unroll 2
    for (int dd = 0; dd < 128; dd++) {
        float a[8], bb[8];
        #pragma unroll
        for (int i = 0; i < 8; i++) a[i]  = s_q[(c0 + i)*129 + dd];
        #pragma unroll
        for (int j = 0; j < 8; j++) bb[j] = s_B[(k0 + j)*129 + dd];
        #pragma unroll
        for (int i = 0; i < 8; i++)
            #pragma unroll
            for (int j = 0; j < 8; j++)
                acc[i][j] = fmaf(a[i], bb[j], acc[i][j]);
    }
    __syncthreads();   // kf fully consumed

    // write masked A into s_B (overwriting kf)
    #pragma unroll
    for (int i = 0; i < 8; i++)
        #pragma unroll
        for (int j = 0; j < 8; j++) {
            float v = ((k0 + j) <= (c0 + i)) ? acc[i][j] : 0.f;
            s_B[(c0 + i)*129 + k0 + j] = v;
            acc[i][j] = 0.f;   // reset for phase 4
        }
    __syncthreads();

    // z normalizers (threads 0..127; others fall through to phase-4 loads)
    if (t < 128) {
        float z = EPS_;
        const float* arow = s_B + t*129;
        #pragma unroll 4
        for (int k = 0; k < 128; k++) z += arow[k];
        const float* qrow = s_q + t*129;
        #pragma unroll 4
        for (int d2 = 0; d2 < 128; d2++) z += qrow[d2] * s_ks[d2];
        s_z[t] = z;
    }

    // Phase 4: acc = A@v + qf@kv_ex  (256-deep reduction in tiles of 16)
    for (int rt = 0; rt < 16; rt++) {
        #pragma unroll
        for (int rep = 0; rep < 8; rep++) {
            int lin = t + rep*256;
            int row = lin >> 7, e = lin & 127;
            float v;
            if (rt < 8)
                v = g_v [base + (size_t)(rt*16 + row)*HID_ + e];
            else
                v = g_kv[kvb + (size_t)((rt - 8)*16 + row)*D_ + e];
            s_t[row*129 + e] = v;
        }
        __syncthreads();

        const float* op1 = (rt < 8) ? s_B : s_q;
        const int colb = (rt*16) & 127;
        #pragma unroll 4
        for (int rr = 0; rr < 16; rr++) {
            int col = colb + rr;
            float a[8], bb[8];
            #pragma unroll
            for (int i = 0; i < 8; i++) a[i]  = op1[(c0 + i)*129 + col];
            #pragma unroll
            for (int j = 0; j < 8; j++) bb[j] = s_t[rr*129 + k0 + j];
            #pragma unroll
            for (int i = 0; i < 8; i++)
                #pragma unroll
                for (int j = 0; j < 8; j++)
                    acc[i][j] = fmaf(a[i], bb[j], acc[i][j]);
        }
        __syncthreads();
    }

    // normalize + store
    float zz[8];
    #pragma unroll
    for (int i = 0; i < 8; i++) zz[i] = s_z[c0 + i];
    #pragma unroll
    for (int i = 0; i < 8; i++) {
        float inv = 1.f / zz[i];
        #pragma unroll
        for (int j = 0; j < 8; j++)
            g_attn[base + (size_t)(c0 + i)*HID_ + k0 + j] = acc[i][j] * inv;
    }
}

// ---------------------------------------------------------------------------
extern "C" void kernel_launch(void* const* d_in, const int* in_sizes, int n_in,
                              void* d_out, int out_size)
{
    const float* x  = (const float*)d_in[0];
    const float* Wq = (const float*)d_in[1];
    const float* bq = (const float*)d_in[2];
    const float* Wk = (const float*)d_in[3];
    const float* bk = (const float*)d_in[4];
    const float* Wv = (const float*)d_in[5];
    const float* bv = (const float*)d_in[6];
    const float* Wo = (const float*)d_in[7];
    const float* bo = (const float*)d_in[8];

    float *p_qf, *p_kf, *p_v, *p_attn;
    cudaGetSymbolAddress((void**)&p_qf,   g_qf);
    cudaGetSymbolAddress((void**)&p_kf,   g_kf);
    cudaGetSymbolAddress((void**)&p_v,    g_v);
    cudaGetSymbolAddress((void**)&p_attn, g_attn);

    const size_t gsmem = (size_t)(2*GBM*ASTR + 2*GBK*BSTR) * sizeof(float); // ~71.7 KB
    const size_t csmem = (size_t)CS_TOT * sizeof(float);                    // ~141 KB
    cudaFuncSetAttribute(gemm_tf32_kernel,
                         cudaFuncAttributeMaxDynamicSharedMemorySize, (int)gsmem);
    cudaFuncSetAttribute(chunk_attn_kernel,
                         cudaFuncAttributeMaxDynamicSharedMemorySize, (int)csmem);

    dim3 gblk(256);
    dim3 ggrid(HID_/GBN, M_/GBM);   // 16 x 64

    // Projections (elu+1 fused for q,k)
    gemm_tf32_kernel<<<ggrid, gblk, gsmem>>>(x, Wq, bq, p_qf, 1);
    gemm_tf32_kernel<<<ggrid, gblk, gsmem>>>(x, Wk, bk, p_kf, 1);
    gemm_tf32_kernel<<<ggrid, gblk, gsmem>>>(x, Wv, bv, p_v, 0);

    // Chunked linear attention
    chunk_kv_kernel<<<B_*H_*NC_, 256>>>();
    scan_kv_kernel<<<(B_*H_*D_*D_)/256, 256>>>();
    scan_ks_kernel<<<(B_*H_*D_)/256, 256>>>();
    chunk_attn_kernel<<<B_*H_*NC_, 256, csmem>>>();

    // Output projection
    gemm_tf32_kernel<<<ggrid, gblk, gsmem>>>(p_attn, Wo, bo, (float*)d_out, 0);
}

// round 5
// speedup vs baseline: 1.0794x; 1.0794x over previous
#include <cuda_runtime.h>
#include <cstdint>

// Problem constants
#define B_   2
#define S_   4096
#define H_   16
#define D_   128
#define HID_ 2048
#define C_   128
#define NC_  32
#define M_   (B_*S_)   // 8192 rows
#define EPS_ 1e-6f

// ---------------- scratch (device globals; no allocs allowed) ----------------
__device__ float g_qf[(size_t)M_*HID_];
__device__ float g_kf[(size_t)M_*HID_];
__device__ float g_v [(size_t)M_*HID_];
__device__ float g_attn[(size_t)M_*HID_];
__device__ float g_kv[(size_t)B_*H_*NC_*D_*D_];   // [B][H][NC][D][D]
__device__ float g_ks[(size_t)B_*H_*NC_*D_];      // [B][H][NC][D]
__device__ float g_xr[(size_t)M_*HID_];           // tf32-rounded x
__device__ float g_Wr[(size_t)4*HID_*HID_];       // tf32-rounded weights

// ============================ helpers ==================================
__device__ __forceinline__ unsigned f2tf(float x) {
    unsigned u; asm("cvt.rna.tf32.f32 %0, %1;" : "=r"(u) : "f"(x)); return u;
}
__device__ __forceinline__ void cpasync16(void* s, const void* g) {
    unsigned sa = (unsigned)__cvta_generic_to_shared(s);
    asm volatile("cp.async.cg.shared.global [%0], [%1], 16;\n" :: "r"(sa), "l"(g));
}

// ---------------------------------------------------------------------------
// Elementwise tf32 rounding (RN): out[i] = round_tf32(in[i])
// ---------------------------------------------------------------------------
__global__ __launch_bounds__(256)
void round_tf32_kernel(const float* __restrict__ in, float* __restrict__ out, int n4)
{
    int i = blockIdx.x * 256 + threadIdx.x;
    if (i < n4) {
        float4 v = ((const float4*)in)[i];
        v.x = __uint_as_float(f2tf(v.x));
        v.y = __uint_as_float(f2tf(v.y));
        v.z = __uint_as_float(f2tf(v.z));
        v.w = __uint_as_float(f2tf(v.w));
        ((float4*)out)[i] = v;
    }
}

// ===========================================================================
// tf32 mma.sync GEMM: out[M,N] = A[M,K] @ W[K,N] + bias (+ elu+1)
// A, W pre-rounded to tf32. BM=BN=128, BK=32, 128 threads (4 warps, 64x64
// warp tiles), 3-stage cp.async pipeline. No cvt in the mainloop.
// ===========================================================================
#define ASTR 36
#define BSTR 136
#define STG_FLTS (128*ASTR + 32*BSTR)     // 8960 floats per stage
#define G_SMEM (3*STG_FLTS*4)             // 107520 bytes
#define G_NKT (HID_/32)                   // 64

extern __shared__ unsigned char smem_raw[];

__device__ __forceinline__ void g_load_stage(float* As, float* Bs,
                                             const float* __restrict__ A,
                                             const float* __restrict__ W,
                                             int bm, int bn, int kt, int t)
{
    const float* Ag = A + (size_t)(bm*128)*HID_ + kt*32;
    #pragma unroll
    for (int rep = 0; rep < 8; rep++) {
        int q = t + rep*128;              // 0..1023
        int r = q >> 3, c4 = (q & 7) * 4;
        cpasync16(&As[r*ASTR + c4], Ag + (size_t)r*HID_ + c4);
    }
    const float* Wg = W + (size_t)(kt*32)*HID_ + bn*128;
    #pragma unroll
    for (int rep = 0; rep < 8; rep++) {
        int q = t + rep*128;
        int k = q >> 5, n4 = (q & 31) * 4;
        cpasync16(&Bs[k*BSTR + n4], Wg + (size_t)k*HID_ + n4);
    }
}

__global__ __launch_bounds__(128)
void gemm_tf32_kernel(const float* __restrict__ A, const float* __restrict__ W,
                      const float* __restrict__ bias, float* __restrict__ out,
                      int act)
{
    float* sm = (float*)smem_raw;
    const int t = threadIdx.x;
    const int lane = t & 31, warp = t >> 5;
    const int wm = warp >> 1, wn = warp & 1;   // 2x2 warps, 64x64 each
    const int g = lane >> 2, tg = lane & 3;
    const int bn = blockIdx.x, bm = blockIdx.y;

    float acc[4][8][4];
    #pragma unroll
    for (int mi = 0; mi < 4; mi++)
        #pragma unroll
        for (int ni = 0; ni < 8; ni++)
            #pragma unroll
            for (int q = 0; q < 4; q++) acc[mi][ni][q] = 0.f;

    #pragma unroll
    for (int st = 0; st < 3; st++) {
        g_load_stage(sm + st*STG_FLTS, sm + st*STG_FLTS + 128*ASTR,
                     A, W, bm, bn, st, t);
        asm volatile("cp.async.commit_group;\n" ::: "memory");
    }

    for (int kt = 0; kt < G_NKT; kt++) {
        const int s = kt % 3;
        if (kt < G_NKT-2)      asm volatile("cp.async.wait_group 2;\n" ::: "memory");
        else if (kt == G_NKT-2) asm volatile("cp.async.wait_group 1;\n" ::: "memory");
        else                    asm volatile("cp.async.wait_group 0;\n" ::: "memory");
        __syncthreads();

        const float* Ab = sm + s*STG_FLTS;
        const float* Bb = Ab + 128*ASTR;

        #pragma unroll
        for (int kk = 0; kk < 4; kk++) {
            unsigned a[4][4], b[8][2];
            #pragma unroll
            for (int mi = 0; mi < 4; mi++) {
                int r0 = wm*64 + mi*16 + g;
                a[mi][0] = __float_as_uint(Ab[ r0      *ASTR + kk*8 + tg    ]);
                a[mi][1] = __float_as_uint(Ab[(r0 + 8) *ASTR + kk*8 + tg    ]);
                a[mi][2] = __float_as_uint(Ab[ r0      *ASTR + kk*8 + tg + 4]);
                a[mi][3] = __float_as_uint(Ab[(r0 + 8) *ASTR + kk*8 + tg + 4]);
            }
            #pragma unroll
            for (int ni = 0; ni < 8; ni++) {
                int c0 = wn*64 + ni*8 + g;
                b[ni][0] = __float_as_uint(Bb[(kk*8 + tg    )*BSTR + c0]);
                b[ni][1] = __float_as_uint(Bb[(kk*8 + tg + 4)*BSTR + c0]);
            }
            #pragma unroll
            for (int mi = 0; mi < 4; mi++)
                #pragma unroll
                for (int ni = 0; ni < 8; ni++) {
                    asm volatile(
                        "mma.sync.aligned.m16n8k8.row.col.f32.tf32.tf32.f32 "
                        "{%0,%1,%2,%3},{%4,%5,%6,%7},{%8,%9},{%0,%1,%2,%3};\n"
                        : "+f"(acc[mi][ni][0]), "+f"(acc[mi][ni][1]),
                          "+f"(acc[mi][ni][2]), "+f"(acc[mi][ni][3])
                        : "r"(a[mi][0]), "r"(a[mi][1]), "r"(a[mi][2]), "r"(a[mi][3]),
                          "r"(b[ni][0]), "r"(b[ni][1]));
                }
        }
        __syncthreads();

        if (kt + 3 < G_NKT) {
            g_load_stage(sm + s*STG_FLTS, sm + s*STG_FLTS + 128*ASTR,
                         A, W, bm, bn, kt + 3, t);
            asm volatile("cp.async.commit_group;\n" ::: "memory");
        }
    }

    // epilogue
    #pragma unroll
    for (int mi = 0; mi < 4; mi++) {
        int row0 = bm*128 + wm*64 + mi*16 + g;
        #pragma unroll
        for (int ni = 0; ni < 8; ni++) {
            int col = bn*128 + wn*64 + ni*8 + 2*tg;
            float b0 = bias[col], b1 = bias[col + 1];
            float v0 = acc[mi][ni][0] + b0;
            float v1 = acc[mi][ni][1] + b1;
            float v2 = acc[mi][ni][2] + b0;
            float v3 = acc[mi][ni][3] + b1;
            if (act) {
                v0 = (v0 > 0.f) ? v0 + 1.f : __expf(v0);
                v1 = (v1 > 0.f) ? v1 + 1.f : __expf(v1);
                v2 = (v2 > 0.f) ? v2 + 1.f : __expf(v2);
                v3 = (v3 > 0.f) ? v3 + 1.f : __expf(v3);
            }
            float2 p0; p0.x = v0; p0.y = v1;
            float2 p1; p1.x = v2; p1.y = v3;
            *(float2*)&out[(size_t) row0     *HID_ + col] = p0;
            *(float2*)&out[(size_t)(row0 + 8)*HID_ + col] = p1;
        }
    }
}

// ---------------------------------------------------------------------------
// Chunk KV: per (b,h,n): kv[d,e] = sum_c kf[c,d]*v[c,e]; ksum[d] = sum_c kf[c,d]
// ---------------------------------------------------------------------------
__global__ __launch_bounds__(256)
void chunk_kv_kernel()
{
    __shared__ float skf[16*129];
    __shared__ float sv [16*129];

    const int t = threadIdx.x;
    const int lane = t & 31, warp = t >> 5;
    const int tdw = lane >> 3, tew = lane & 7;
    const int wd  = warp >> 1, we  = warp & 1;
    const int d0 = (wd*4 + tdw) * 8;
    const int e0 = (we*8 + tew) * 8;

    const int x = blockIdx.x;
    const int b = x / (H_*NC_);
    const int r = x % (H_*NC_);
    const int h = r / NC_;
    const int n = r % NC_;

    const size_t base = ((size_t)(b*S_ + n*C_))*HID_ + h*D_;

    float acc[8][8];
    float ks[8];
    #pragma unroll
    for (int i = 0; i < 8; i++) { ks[i] = 0.f;
        #pragma unroll
        for (int j = 0; j < 8; j++) acc[i][j] = 0.f; }

    for (int ct = 0; ct < 8; ct++) {
        #pragma unroll
        for (int rep = 0; rep < 8; rep++) {
            int lin = t + rep*256;
            int row = lin >> 7, d = lin & 127;
            size_t ga = base + (size_t)(ct*16 + row)*HID_ + d;
            skf[row*129 + d] = g_kf[ga];
            sv [row*129 + d] = g_v [ga];
        }
        __syncthreads();
        #pragma unroll 4
        for (int cc = 0; cc < 16; cc++) {
            float a[8], bb[8];
            #pragma unroll
            for (int i = 0; i < 8; i++) a[i]  = skf[cc*129 + d0 + i];
            #pragma unroll
            for (int j = 0; j < 8; j++) bb[j] = sv [cc*129 + e0 + j];
            #pragma unroll
            for (int i = 0; i < 8; i++) {
                ks[i] += a[i];
                #pragma unroll
                for (int j = 0; j < 8; j++)
                    acc[i][j] = fmaf(a[i], bb[j], acc[i][j]);
            }
        }
        __syncthreads();
    }

    const size_t kvb = (size_t)x * (D_*D_);
    #pragma unroll
    for (int i = 0; i < 8; i++)
        #pragma unroll
        for (int j = 0; j < 8; j++)
            g_kv[kvb + (size_t)(d0 + i)*D_ + e0 + j] = acc[i][j];

    if (we == 0 && tew == 0) {
        #pragma unroll
        for (int i = 0; i < 8; i++)
            g_ks[(size_t)x*D_ + d0 + i] = ks[i];
    }
}

// ---------------------------------------------------------------------------
// In-place exclusive scans over the chunk axis
// ---------------------------------------------------------------------------
__global__ __launch_bounds__(256)
void scan_kv_kernel()
{
    int f = blockIdx.x * 256 + threadIdx.x;
    int bh = f >> 14;
    int de = f & 16383;
    float* p = g_kv + (size_t)bh * (NC_*D_*D_) + de;
    float run = 0.f;
    #pragma unroll
    for (int n = 0; n < NC_; n++) {
        float tv = p[(size_t)n * (D_*D_)];
        p[(size_t)n * (D_*D_)] = run;
        run += tv;
    }
}

__global__ __launch_bounds__(256)
void scan_ks_kernel()
{
    int f = blockIdx.x * 256 + threadIdx.x;
    int bh = f >> 7;
    int d  = f & 127;
    float* p = g_ks + (size_t)bh * (NC_*D_) + d;
    float run = 0.f;
    #pragma unroll
    for (int n = 0; n < NC_; n++) {
        float tv = p[n*D_];
        p[n*D_] = run;
        run += tv;
    }
}

// ---------------------------------------------------------------------------
// Per-chunk attention (fp32 SIMT); stores tf32-rounded for the out-proj GEMM
// ---------------------------------------------------------------------------
#define CS_Q   0
#define CS_B   (128*129)
#define CS_T   (2*128*129)
#define CS_KS  (2*128*129 + 16*129)
#define CS_Z   (CS_KS + 128)
#define CS_TOT (CS_Z + 128)

__global__ __launch_bounds__(256)
void chunk_attn_kernel()
{
    float* cs = (float*)smem_raw;
    float* s_q  = cs + CS_Q;
    float* s_B  = cs + CS_B;
    float* s_t  = cs + CS_T;
    float* s_ks = cs + CS_KS;
    float* s_z  = cs + CS_Z;

    const int t = threadIdx.x;
    const int lane = t & 31, warp = t >> 5;
    const int tcw = lane >> 3, tkw = lane & 7;
    const int wc  = warp >> 1, wk  = warp & 1;
    const int c0 = (wc*4 + tcw) * 8;
    const int k0 = (wk*8 + tkw) * 8;

    const int x = blockIdx.x;
    const int b = x / (H_*NC_);
    const int r = x % (H_*NC_);
    const int h = r / NC_;
    const int n = r % NC_;

    const size_t base = ((size_t)(b*S_ + n*C_))*HID_ + h*D_;
    const size_t kvb  = (size_t)x * (D_*D_);

    #pragma unroll
    for (int rep = 0; rep < 64; rep++) {
        int lin = t + rep*256;
        int row = lin >> 7, d = lin & 127;
        size_t ga = base + (size_t)row*HID_ + d;
        s_q[row*129 + d] = g_qf[ga];
        s_B[row*129 + d] = g_kf[ga];
    }
    if (t < 128) s_ks[t] = g_ks[(size_t)x*D_ + t];
    __syncthreads();

    float acc[8][8];
    #pragma unroll
    for (int i = 0; i < 8; i++)
        #pragma unroll
        for (int j = 0; j < 8; j++) acc[i][j] = 0.f;

    #pragma unroll 2
    for (int dd = 0; dd < 128; dd++) {
        float a[8], bb[8];
        #pragma unroll
        for (int i = 0; i < 8; i++) a[i]  = s_q[(c0 + i)*129 + dd];
        #pragma unroll
        for (int j = 0; j < 8; j++) bb[j] = s_B[(k0 + j)*129 + dd];
        #pragma unroll
        for (int i = 0; i < 8; i++)
            #pragma unroll
            for (int j = 0; j < 8; j++)
                acc[i][j] = fmaf(a[i], bb[j], acc[i][j]);
    }
    __syncthreads();

    #pragma unroll
    for (int i = 0; i < 8; i++)
        #pragma unroll
        for (int j = 0; j < 8; j++) {
            float v = ((k0 + j) <= (c0 + i)) ? acc[i][j] : 0.f;
            s_B[(c0 + i)*129 + k0 + j] = v;
            acc[i][j] = 0.f;
        }
    __syncthreads();

    if (t < 128) {
        float z = EPS_;
        const float* arow = s_B + t*129;
        #pragma unroll 4
        for (int k = 0; k < 128; k++) z += arow[k];
        const float* qrow = s_q + t*129;
        #pragma unroll 4
        for (int d2 = 0; d2 < 128; d2++) z += qrow[d2] * s_ks[d2];
        s_z[t] = z;
    }

    for (int rt = 0; rt < 16; rt++) {
        #pragma unroll
        for (int rep = 0; rep < 8; rep++) {
            int lin = t + rep*256;
            int row = lin >> 7, e = lin & 127;
            float v;
            if (rt < 8)
                v = g_v [base + (size_t)(rt*16 + row)*HID_ + e];
            else
                v = g_kv[kvb + (size_t)((rt - 8)*16 + row)*D_ + e];
            s_t[row*129 + e] = v;
        }
        __syncthreads();

        const float* op1 = (rt < 8) ? s_B : s_q;
        const int colb = (rt*16) & 127;
        #pragma unroll 4
        for (int rr = 0; rr < 16; rr++) {
            int col = colb + rr;
            float a[8], bb[8];
            #pragma unroll
            for (int i = 0; i < 8; i++) a[i]  = op1[(c0 + i)*129 + col];
            #pragma unroll
            for (int j = 0; j < 8; j++) bb[j] = s_t[rr*129 + k0 + j];
            #pragma unroll
            for (int i = 0; i < 8; i++)
                #pragma unroll
                for (int j = 0; j < 8; j++)
                    acc[i][j] = fmaf(a[i], bb[j], acc[i][j]);
        }
        __syncthreads();
    }

    float zz[8];
    #pragma unroll
    for (int i = 0; i < 8; i++) zz[i] = s_z[c0 + i];
    #pragma unroll
    for (int i = 0; i < 8; i++) {
        float inv = 1.f / zz[i];
        #pragma unroll
        for (int j = 0; j < 8; j++)
            g_attn[base + (size_t)(c0 + i)*HID_ + k0 + j] =
                __uint_as_float(f2tf(acc[i][j] * inv));
    }
}

// ---------------------------------------------------------------------------
extern "C" void kernel_launch(void* const* d_in, const int* in_sizes, int n_in,
                              void* d_out, int out_size)
{
    const float* x  = (const float*)d_in[0];
    const float* Wq = (const float*)d_in[1];
    const float* bq = (const float*)d_in[2];
    const float* Wk = (const float*)d_in[3];
    const float* bk = (const float*)d_in[4];
    const float* Wv = (const float*)d_in[5];
    const float* bv = (const float*)d_in[6];
    const float* Wo = (const float*)d_in[7];
    const float* bo = (const float*)d_in[8];

    float *p_qf, *p_kf, *p_v, *p_attn, *p_xr, *p_Wr;
    cudaGetSymbolAddress((void**)&p_qf,   g_qf);
    cudaGetSymbolAddress((void**)&p_kf,   g_kf);
    cudaGetSymbolAddress((void**)&p_v,    g_v);
    cudaGetSymbolAddress((void**)&p_attn, g_attn);
    cudaGetSymbolAddress((void**)&p_xr,   g_xr);
    cudaGetSymbolAddress((void**)&p_Wr,   g_Wr);

    const size_t csmem = (size_t)CS_TOT * sizeof(float);
    cudaFuncSetAttribute(gemm_tf32_kernel,
                         cudaFuncAttributeMaxDynamicSharedMemorySize, G_SMEM);
    cudaFuncSetAttribute(chunk_attn_kernel,
                         cudaFuncAttributeMaxDynamicSharedMemorySize, (int)csmem);

    const size_t WSZ = (size_t)HID_ * HID_;

    // pre-round x and weights to tf32 (removes all cvt from the GEMM mainloop)
    int xn4 = (int)((size_t)M_*HID_/4);
    int wn4 = (int)(WSZ/4);
    round_tf32_kernel<<<(xn4+255)/256, 256>>>(x,  p_xr, xn4);
    round_tf32_kernel<<<(wn4+255)/256, 256>>>(Wq, p_Wr + 0*WSZ, wn4);
    round_tf32_kernel<<<(wn4+255)/256, 256>>>(Wk, p_Wr + 1*WSZ, wn4);
    round_tf32_kernel<<<(wn4+255)/256, 256>>>(Wv, p_Wr + 2*WSZ, wn4);
    round_tf32_kernel<<<(wn4+255)/256, 256>>>(Wo, p_Wr + 3*WSZ, wn4);

    dim3 gg(HID_/128, M_/128);   // (16, 64)

    gemm_tf32_kernel<<<gg, 128, G_SMEM>>>(p_xr, p_Wr + 0*WSZ, bq, p_qf, 1);
    gemm_tf32_kernel<<<gg, 128, G_SMEM>>>(p_xr, p_Wr + 1*WSZ, bk, p_kf, 1);
    gemm_tf32_kernel<<<gg, 128, G_SMEM>>>(p_xr, p_Wr + 2*WSZ, bv, p_v, 0);

    chunk_kv_kernel<<<B_*H_*NC_, 256>>>();
    scan_kv_kernel<<<(B_*H_*D_*D_)/256, 256>>>();
    scan_ks_kernel<<<(B_*H_*D_)/256, 256>>>();
    chunk_attn_kernel<<<B_*H_*NC_, 256, csmem>>>();

    gemm_tf32_kernel<<<gg, 128, G_SMEM>>>(p_attn, p_Wr + 3*WSZ, bo, (float*)d_out, 0);
}